// round 12
// baseline (speedup 1.0000x reference)
#include <cuda_runtime.h>
#include <cuda_fp16.h>

#define N_NODES 50000
#define N_EDGES 800000
#define C 128
#define EDGE_DIM 8
#define N_LAYERS 3

#define SCAN_BLK 512
#define SCAN_NB ((N_NODES + SCAN_BLK - 1) / SCAN_BLK)   // 98

// ---------------------------------------------------------------------------
// Scratch (device globals). All fully recomputed every launch.
// ---------------------------------------------------------------------------
__device__ int   g_esrc[N_EDGES];                    // src node, grouped by dst
__device__ float g_ewl[N_LAYERS * N_EDGES];          // per-layer weight, grouped by dst
__device__ int   g_deg[N_NODES];
__device__ int   g_off[N_NODES];
__device__ int   g_cur[N_NODES];
__device__ int   g_bsum[SCAN_NB];
__device__ __align__(16) __half g_y[N_NODES * C];    // y = x @ W, fp16 staged
__device__ __align__(16) float g_xbuf0[N_NODES * C];
__device__ __align__(16) float g_xbuf1[N_NODES * C];

// ---------------------------------------------------------------------------
// Packed fp32x2 helpers (Blackwell; ptxas never emits FFMA2 from C++)
// ---------------------------------------------------------------------------
__device__ __forceinline__ unsigned long long pack2(float lo, float hi) {
    unsigned long long r;
    asm("mov.b64 %0, {%1, %2};" : "=l"(r) : "f"(lo), "f"(hi));
    return r;
}
__device__ __forceinline__ void fma2(unsigned long long& d,
                                     unsigned long long a,
                                     unsigned long long b) {
    asm("fma.rn.f32x2 %0, %1, %2, %3;" : "=l"(d) : "l"(a), "l"(b), "l"(d));
}
__device__ __forceinline__ void unpack2(unsigned long long v, float& lo, float& hi) {
    asm("mov.b64 {%0, %1}, %2;" : "=f"(lo), "=f"(hi) : "l"(v));
}

// ---------------------------------------------------------------------------
// CSR build
// ---------------------------------------------------------------------------
__global__ void zero_deg_kernel() {
    int i = blockIdx.x * blockDim.x + threadIdx.x;
    if (i < N_NODES) g_deg[i] = 0;
}

__global__ void count_kernel(const int* __restrict__ ei) {
    int q = blockIdx.x * blockDim.x + threadIdx.x;      // int4 index
    if (q * 4 >= N_EDGES) return;
    int4 d4 = __ldg((const int4*)(ei + N_EDGES) + q);
    atomicAdd(&g_deg[d4.x], 1);
    atomicAdd(&g_deg[d4.y], 1);
    atomicAdd(&g_deg[d4.z], 1);
    atomicAdd(&g_deg[d4.w], 1);
}

__global__ void scan_a_kernel() {
    __shared__ int sh[SCAN_BLK];
    int t = threadIdx.x;
    int i = blockIdx.x * SCAN_BLK + t;
    int v = (i < N_NODES) ? g_deg[i] : 0;
    sh[t] = v;
    __syncthreads();
    for (int off = 1; off < SCAN_BLK; off <<= 1) {
        int add = (t >= off) ? sh[t - off] : 0;
        __syncthreads();
        sh[t] += add;
        __syncthreads();
    }
    if (i < N_NODES) g_off[i] = sh[t] - v;
    if (t == SCAN_BLK - 1) g_bsum[blockIdx.x] = sh[t];
}

__global__ void scan_b_kernel() {
    __shared__ int sh[128];
    int t = threadIdx.x;
    int v = (t < SCAN_NB) ? g_bsum[t] : 0;
    sh[t] = v;
    __syncthreads();
    for (int off = 1; off < 128; off <<= 1) {
        int add = (t >= off) ? sh[t - off] : 0;
        __syncthreads();
        sh[t] += add;
        __syncthreads();
    }
    if (t < SCAN_NB) g_bsum[t] = sh[t] - v;
}

__global__ void scan_c_kernel() {
    int i = blockIdx.x * blockDim.x + threadIdx.x;
    if (i < N_NODES) {
        int o = g_off[i] + g_bsum[i / SCAN_BLK];
        g_off[i] = o;
        g_cur[i] = o;
    }
}

__global__ void fill_kernel(const int* __restrict__ ei,
                            const float* __restrict__ ea,
                            const float* __restrict__ ew,
                            const float* __restrict__ eb) {
    int e = blockIdx.x * blockDim.x + threadIdx.x;
    if (e >= N_EDGES) return;
    int s = __ldg(ei + e);
    int d = __ldg(ei + N_EDGES + e);
    const float4* ap = (const float4*)(ea + (size_t)e * EDGE_DIM);
    float4 a0 = ap[0];
    float4 a1 = ap[1];
    float w[N_LAYERS];
#pragma unroll
    for (int l = 0; l < N_LAYERS; l++) {
        const float* wl = ew + l * EDGE_DIM;
        float z = a0.x * wl[0] + a0.y * wl[1] + a0.z * wl[2] + a0.w * wl[3] +
                  a1.x * wl[4] + a1.y * wl[5] + a1.z * wl[6] + a1.w * wl[7] + eb[l];
        w[l] = (z > 20.0f) ? z : log1pf(__expf(z));
    }
    int pos = atomicAdd(&g_cur[d], 1);
    g_esrc[pos] = s;
#pragma unroll
    for (int l = 0; l < N_LAYERS; l++) g_ewl[l * N_EDGES + pos] = w[l];
}

// ---------------------------------------------------------------------------
// Aggregation over fp16 y = x@W, fp32 accumulation, fused epilogue.
// Warp per node:
//   out[v] = f( sum_e w_e*y[src_e] - (sum_e w_e)*y[v] + b )
//   f = relu(.)+xres[v]   (layers 0,1)   or identity (layer 2)
// ---------------------------------------------------------------------------
__device__ __forceinline__ void acc_edge(float4& acc, float w, uint2 raw) {
    float2 f0 = __half22float2(*(__half2*)&raw.x);
    float2 f1 = __half22float2(*(__half2*)&raw.y);
    acc.x += w * f0.x; acc.y += w * f0.y;
    acc.z += w * f1.x; acc.w += w * f1.y;
}

template <int LAYER, int RELU_RES>
__global__ __launch_bounds__(256) void agg_kernel(const __half* __restrict__ y,
                                                  const float* __restrict__ xres,
                                                  const float* __restrict__ bias,
                                                  float* __restrict__ out) {
    int node = (int)((blockIdx.x * (unsigned)blockDim.x + threadIdx.x) >> 5);
    int lane = threadIdx.x & 31;
    if (node >= N_NODES) return;

    int beg = g_off[node];
    int end = beg + g_deg[node];

    float4 acc = make_float4(0.f, 0.f, 0.f, 0.f);
    float swsum = 0.0f;

    for (int j = beg; j < end; j += 32) {
        int   sedge = 0;
        float wedge = 0.0f;
        if (j + lane < end) {
            sedge = __ldg(g_esrc + j + lane);
            wedge = __ldg(g_ewl + (size_t)LAYER * N_EDGES + j + lane);
        }
        int cnt = min(32, end - j);
        int t = 0;
        for (; t + 4 <= cnt; t += 4) {
            int   s0 = __shfl_sync(0xffffffffu, sedge, t + 0);
            int   s1 = __shfl_sync(0xffffffffu, sedge, t + 1);
            int   s2 = __shfl_sync(0xffffffffu, sedge, t + 2);
            int   s3 = __shfl_sync(0xffffffffu, sedge, t + 3);
            float w0 = __shfl_sync(0xffffffffu, wedge, t + 0);
            float w1 = __shfl_sync(0xffffffffu, wedge, t + 1);
            float w2 = __shfl_sync(0xffffffffu, wedge, t + 2);
            float w3 = __shfl_sync(0xffffffffu, wedge, t + 3);
            uint2 r0 = __ldg((const uint2*)(y + (size_t)s0 * C) + lane);
            uint2 r1 = __ldg((const uint2*)(y + (size_t)s1 * C) + lane);
            uint2 r2 = __ldg((const uint2*)(y + (size_t)s2 * C) + lane);
            uint2 r3 = __ldg((const uint2*)(y + (size_t)s3 * C) + lane);
            acc_edge(acc, w0, r0);
            acc_edge(acc, w1, r1);
            acc_edge(acc, w2, r2);
            acc_edge(acc, w3, r3);
            swsum += w0 + w1 + w2 + w3;
        }
        for (; t < cnt; t++) {
            int   s  = __shfl_sync(0xffffffffu, sedge, t);
            float wt = __shfl_sync(0xffffffffu, wedge, t);
            uint2 r = __ldg((const uint2*)(y + (size_t)s * C) + lane);
            acc_edge(acc, wt, r);
            swsum += wt;
        }
    }

    uint2 rv = __ldg((const uint2*)(y + (size_t)node * C) + lane);
    float2 yv0 = __half22float2(*(__half2*)&rv.x);
    float2 yv1 = __half22float2(*(__half2*)&rv.y);
    float4 bb = __ldg((const float4*)(bias) + lane);
    float4 v;
    v.x = acc.x - swsum * yv0.x + bb.x;
    v.y = acc.y - swsum * yv0.y + bb.y;
    v.z = acc.z - swsum * yv1.x + bb.z;
    v.w = acc.w - swsum * yv1.y + bb.w;
    if (RELU_RES) {
        float4 r = __ldg((const float4*)(xres + (size_t)node * C) + lane);
        v.x = fmaxf(v.x, 0.f) + r.x;
        v.y = fmaxf(v.y, 0.f) + r.y;
        v.z = fmaxf(v.z, 0.f) + r.z;
        v.w = fmaxf(v.w, 0.f) + r.w;
    }
    *((float4*)(out + (size_t)node * C) + lane) = v;
}

// ---------------------------------------------------------------------------
// SGEMM: y[M,C] = X[M,C] @ W[C,C], fp32 compute via packed fma.rn.f32x2,
// fp16 output. 128x128 tile, BK=16, 256 threads, 8x8/thread.
// ---------------------------------------------------------------------------
#define GBM 128
#define GBK 16

__global__ __launch_bounds__(256) void gemm_kernel(const float* __restrict__ X,
                                                   const float* __restrict__ W,
                                                   __half* __restrict__ Y) {
    __shared__ float As[GBK][GBM + 4];
    __shared__ float Ws[GBK][GBM];

    int t = threadIdx.x;
    int tx = t & 15, ty = t >> 4;
    int m0 = blockIdx.x * GBM;

    int arow[2], akq[2], wk[2], wn[2];
#pragma unroll
    for (int i = 0; i < 2; i++) {
        int idx = t + 256 * i;
        arow[i] = idx >> 2;
        akq[i]  = idx & 3;
        wk[i]   = idx >> 5;
        wn[i]   = (idx & 31) << 2;
    }

    // Packed accumulators: acc2[i][j2] holds columns (2*j2, 2*j2+1) of the
    // thread's 8-wide j-range (j2 0,1 -> cols tx*4+0..3 ; j2 2,3 -> +64).
    unsigned long long acc2[8][4];
#pragma unroll
    for (int i = 0; i < 8; i++)
#pragma unroll
        for (int j = 0; j < 4; j++) acc2[i][j] = 0ull;

    float4 pa[2], pw[2];
#pragma unroll
    for (int i = 0; i < 2; i++) {
        int gm = m0 + arow[i];
        pa[i] = (gm < N_NODES)
                    ? __ldg((const float4*)(X + (size_t)gm * C + akq[i] * 4))
                    : make_float4(0.f, 0.f, 0.f, 0.f);
        pw[i] = __ldg((const float4*)(W + (size_t)wk[i] * C + wn[i]));
    }

    for (int kc = 0; kc < C; kc += GBK) {
#pragma unroll
        for (int i = 0; i < 2; i++) {
            int kb = akq[i] * 4;
            As[kb + 0][arow[i]] = pa[i].x;
            As[kb + 1][arow[i]] = pa[i].y;
            As[kb + 2][arow[i]] = pa[i].z;
            As[kb + 3][arow[i]] = pa[i].w;
            *(float4*)&Ws[wk[i]][wn[i]] = pw[i];
        }
        __syncthreads();

        if (kc + GBK < C) {
#pragma unroll
            for (int i = 0; i < 2; i++) {
                int gm = m0 + arow[i];
                pa[i] = (gm < N_NODES)
                            ? __ldg((const float4*)(X + (size_t)gm * C +
                                                    (kc + GBK) + akq[i] * 4))
                            : make_float4(0.f, 0.f, 0.f, 0.f);
                pw[i] = __ldg((const float4*)(W + (size_t)(kc + GBK + wk[i]) * C +
                                              wn[i]));
            }
        }

#pragma unroll
        for (int k = 0; k < GBK; k++) {
            float4 a0 = *(const float4*)&As[k][ty * 4];
            float4 a1 = *(const float4*)&As[k][ty * 4 + 64];
            float4 b0 = *(const float4*)&Ws[k][tx * 4];
            float4 b1 = *(const float4*)&Ws[k][tx * 4 + 64];
            unsigned long long bs[4];
            bs[0] = pack2(b0.x, b0.y);
            bs[1] = pack2(b0.z, b0.w);
            bs[2] = pack2(b1.x, b1.y);
            bs[3] = pack2(b1.z, b1.w);
            float av[8] = {a0.x, a0.y, a0.z, a0.w, a1.x, a1.y, a1.z, a1.w};
#pragma unroll
            for (int i = 0; i < 8; i++) {
                unsigned long long as = pack2(av[i], av[i]);
#pragma unroll
                for (int j = 0; j < 4; j++) fma2(acc2[i][j], as, bs[j]);
            }
        }
        __syncthreads();
    }

#pragma unroll
    for (int hi = 0; hi < 2; hi++) {
#pragma unroll
        for (int ii = 0; ii < 4; ii++) {
            int m = m0 + ty * 4 + ii + hi * 64;
            if (m >= N_NODES) continue;
            int ai = hi * 4 + ii;
#pragma unroll
            for (int hj = 0; hj < 2; hj++) {
                int n = tx * 4 + hj * 64;
                float c0, c1, c2, c3;
                unpack2(acc2[ai][hj * 2 + 0], c0, c1);
                unpack2(acc2[ai][hj * 2 + 1], c2, c3);
                __half2 p0 = __floats2half2_rn(c0, c1);
                __half2 p1 = __floats2half2_rn(c2, c3);
                uint2 u;
                u.x = *(unsigned*)&p0;
                u.y = *(unsigned*)&p1;
                *(uint2*)(Y + (size_t)m * C + n) = u;
            }
        }
    }
}

// ---------------------------------------------------------------------------
extern "C" void kernel_launch(void* const* d_in, const int* in_sizes, int n_in,
                              void* d_out, int out_size) {
    const float* x  = (const float*)d_in[0];
    const int*   ei = (const int*)d_in[1];
    const float* ea = (const float*)d_in[2];
    const float* lw = (const float*)d_in[3];
    const float* lb = (const float*)d_in[4];
    const float* ew = (const float*)d_in[5];
    const float* eb = (const float*)d_in[6];
    float* out = (float*)d_out;

    __half* yA;
    float *xb0, *xb1;
    cudaGetSymbolAddress((void**)&yA, g_y);
    cudaGetSymbolAddress((void**)&xb0, g_xbuf0);
    cudaGetSymbolAddress((void**)&xb1, g_xbuf1);

    const int NODE_BLOCKS = (N_NODES + 255) / 256;
    const int EDGE_BLOCKS = (N_EDGES + 255) / 256;
    const int CNT_BLOCKS  = (N_EDGES / 4 + 255) / 256;
    const int AGG_BLOCKS  = (N_NODES + 7) / 8;        // warp/node, 8 warps/blk
    const int GM_BLOCKS   = (N_NODES + GBM - 1) / GBM;

    // One-time lazy creation of the side stream + fork/join events (created
    // outside capture on the correctness call; reused on the capture call).
    struct Res {
        cudaStream_t s2;
        cudaEvent_t evFork, evJoin;
        Res() {
            cudaStreamCreateWithFlags(&s2, cudaStreamNonBlocking);
            cudaEventCreateWithFlags(&evFork, cudaEventDisableTiming);
            cudaEventCreateWithFlags(&evJoin, cudaEventDisableTiming);
        }
    };
    static Res r;

    // Fork: gemm0 (y0 = x@W0) runs concurrently with the CSR build.
    cudaEventRecord(r.evFork, 0);
    cudaStreamWaitEvent(r.s2, r.evFork, 0);
    gemm_kernel<<<GM_BLOCKS, 256, 0, r.s2>>>(x, lw, yA);
    cudaEventRecord(r.evJoin, r.s2);

    // CSR build (by dst) + per-edge softplus weights, on the capture stream.
    zero_deg_kernel<<<NODE_BLOCKS, 256>>>();
    count_kernel<<<CNT_BLOCKS, 256>>>(ei);
    scan_a_kernel<<<SCAN_NB, SCAN_BLK>>>();
    scan_b_kernel<<<1, 128>>>();
    scan_c_kernel<<<NODE_BLOCKS, 256>>>();
    fill_kernel<<<EDGE_BLOCKS, 256>>>(ei, ea, ew, eb);

    cudaStreamWaitEvent(0, r.evJoin, 0);

    // layer 0: agg over y0, relu+residual(x) -> xb0
    agg_kernel<0, 1><<<AGG_BLOCKS, 256>>>(yA, x, lb, xb0);

    // layer 1
    gemm_kernel<<<GM_BLOCKS, 256>>>(xb0, lw + C * C, yA);
    agg_kernel<1, 1><<<AGG_BLOCKS, 256>>>(yA, xb0, lb + C, xb1);

    // layer 2 (no relu/residual)
    gemm_kernel<<<GM_BLOCKS, 256>>>(xb1, lw + 2 * C * C, yA);
    agg_kernel<2, 0><<<AGG_BLOCKS, 256>>>(yA, xb1, lb + 2 * C, out);
}